// round 17
// baseline (speedup 1.0000x reference)
#include <cuda_runtime.h>
#include <math_constants.h>

// Shapes (fixed): x: [B=32, C=256, H=128, W=128] float32
#define B_   32
#define C_   256
#define HW_  16384   // 128*128
#define HW4_ 4096    // HW/4 (float4 groups)

#define NPROD 64     // producer CTAs (4 channels each per batch)
#define NCONS 64     // consumer CTAs (each owns 64 float4 columns, EVERY batch)
#define NCTA  (NPROD + NCONS)   // 128 CTAs x 512thr: 1 per SM, all co-resident
#define CAPB  4      // producer lead: live L2 set ~ 5*16MB = 80MB < 126MB

#define HIST_BLOCKS 64

// Scratch (device globals — no allocation; zero-initialized at load)
__device__ float g_pooled[B_ * C_];     // 32 KB
__device__ float g_ssum[NCONS];         // sigmoid partial per consumer CTA
__device__ float g_entro[HW_];          // 64 KB (each column: ONE owner CTA)
__device__ float g_mm[NCONS * 2];       // per-consumer (min,max)
__device__ int   g_hist[256];
__device__ int   g_cnt;
__device__ int   g_done[B_];            // producers finished batch b (count)
__device__ int   g_cons[B_];            // consumers finished batch b (count)

__device__ __forceinline__ void gds() {
#if defined(__CUDA_ARCH__) && (__CUDA_ARCH__ >= 900)
    cudaGridDependencySynchronize();
#endif
}

// ---------------------------------------------------------------------------
// K1 (fused, pipelined, full-chip both roles):
//  CTAs 0..63  (producers): per batch b: pool 4 channels (DRAM), publish,
//              bump g_done[b]. Back-pressure: wait g_cons[b-CAPB]==64.
//  CTAs 64..127 (consumers): EVERY batch: own 64 float4 columns; read the
//              L2-hot 16MB, xn partials via 8 channel-groups + smem combine;
//              owner thread accumulates entro in registers across batches.
//  Flags integer, all float reductions fixed-order -> deterministic.
//  Producer CTA 0 zeroes g_hist for this replay (histout runs after).
// ---------------------------------------------------------------------------
__global__ void __launch_bounds__(512, 1) k_fused(const float* __restrict__ x) {
    const int cta = blockIdx.x;
    const int tid = threadIdx.x;
    const int w   = tid >> 5;
    const int l   = tid & 31;
    const float4* __restrict__ x4 = reinterpret_cast<const float4*>(x);

    if (cta < NPROD) {
        // ----------------------------- producer -----------------------------
        if (cta == 0 && tid < 256) g_hist[tid] = 0;

        __shared__ float sprod[16];
        const int ch_local = w >> 2;     // 0..3
        const int quarter  = w & 3;      // 0..3
        const int ch = cta * 4 + ch_local;

        for (int b = 0; b < B_; b++) {
            if (b >= CAPB) {
                if (tid == 0)
                    while (atomicAdd(&g_cons[b - CAPB], 0) < NCONS) __nanosleep(128);
                __syncthreads();
            }
            const float4* __restrict__ p4 =
                x4 + (size_t)(b * C_ + ch) * HW4_ + quarter * 1024 + l;
            float s = 0.0f;
#pragma unroll 16
            for (int i = 0; i < 32; i++) {
                float4 v = p4[i * 32];
                s += (v.x + v.y) + (v.z + v.w);
            }
#pragma unroll
            for (int o = 16; o > 0; o >>= 1)
                s += __shfl_down_sync(0xffffffffu, s, o);
            if (l == 0) sprod[w] = s;
            __syncthreads();
            if (tid < 4) {
                float t = ((sprod[tid * 4 + 0] + sprod[tid * 4 + 1])
                         + (sprod[tid * 4 + 2] + sprod[tid * 4 + 3]));
                g_pooled[b * C_ + cta * 4 + tid] = t * (1.0f / (float)HW_);
            }
            __syncthreads();
            if (tid == 0) {
                __threadfence();                 // release pooled writes
                atomicAdd(&g_done[b], 1);
            }
        }
    } else {
        // ----------------------------- consumer -----------------------------
        const int q   = cta - NPROD;             // 0..63
        const int col = tid & 63;                // column within slice
        const int cg  = tid >> 6;                // 0..7 channel group (32 ch)
        const int colb = q * 64 + col;           // global float4 column

        __shared__ float  pw[C_];
        __shared__ float4 part[8][64];           // 4 KB
        __shared__ float  swmn[2], swmx[2], swsg[2];

        float4 entro = make_float4(0.f, 0.f, 0.f, 0.f);
        float sig = 0.0f;

        for (int b = 0; b < B_; b++) {
            if (tid == 0) {
                while (atomicAdd(&g_done[b], 0) < NPROD) __nanosleep(128);
                __threadfence();                 // acquire pooled writes
            }
            __syncthreads();
            if (tid < C_) pw[tid] = g_pooled[b * C_ + tid];
            __syncthreads();

            const float4* __restrict__ p4 =
                x4 + ((size_t)(b * C_) + cg * 32) * HW4_ + colb;
            const float* pwg = &pw[cg * 32];
            float ax = 0.f, ay = 0.f, az = 0.f, aw = 0.f;
#pragma unroll 8
            for (int ci = 0; ci < 32; ci++) {
                float4 v = p4[(size_t)ci * HW4_];
                float wt = pwg[ci];
                ax = fmaf(v.x, wt, ax);
                ay = fmaf(v.y, wt, ay);
                az = fmaf(v.z, wt, az);
                aw = fmaf(v.w, wt, aw);
            }
            part[cg][col] = make_float4(ax, ay, az, aw);
            __syncthreads();

            if (tid < 64) {   // owner thread for column tid
                float4 s = part[0][tid];
#pragma unroll
                for (int k = 1; k < 8; k++) {
                    float4 t = part[k][tid];
                    s.x += t.x; s.y += t.y; s.z += t.z; s.w += t.w;
                }
                const float inv = 1.0f / (float)C_;
                float xx = s.x * inv, xy = s.y * inv,
                      xz = s.z * inv, xw = s.w * inv;
                entro.x += xx; entro.y += xy; entro.z += xz; entro.w += xw;
                sig += 1.0f / (1.0f + __expf(-xx))
                     + 1.0f / (1.0f + __expf(-xy))
                     + 1.0f / (1.0f + __expf(-xz))
                     + 1.0f / (1.0f + __expf(-xw));
            }
            __syncthreads();                     // protect part[] / pw[] reuse
            if (tid == 0) atomicAdd(&g_cons[b], 1);  // release L2 window
        }

        // finalize: entro mean over B, min/max, write (column owned: no race)
        float mn = CUDART_INF_F, mx = -CUDART_INF_F;
        if (tid < 64) {
            const float invB = 1.0f / (float)B_;
            float4 e;
            e.x = entro.x * invB; e.y = entro.y * invB;
            e.z = entro.z * invB; e.w = entro.w * invB;
            reinterpret_cast<float4*>(g_entro)[colb] = e;
            mn = fminf(fminf(e.x, e.y), fminf(e.z, e.w));
            mx = fmaxf(fmaxf(e.x, e.y), fmaxf(e.z, e.w));
#pragma unroll
            for (int o = 16; o > 0; o >>= 1) {
                mn  = fminf(mn, __shfl_down_sync(0xffffffffu, mn, o));
                mx  = fmaxf(mx, __shfl_down_sync(0xffffffffu, mx, o));
                sig += __shfl_down_sync(0xffffffffu, sig, o);
            }
            if (l == 0) { swmn[w] = mn; swmx[w] = mx; swsg[w] = sig; }
        }
        __syncthreads();
        if (tid == 0) {
            g_mm[q * 2 + 0] = fminf(swmn[0], swmn[1]);
            g_mm[q * 2 + 1] = fmaxf(swmx[0], swmx[1]);
            g_ssum[q] = swsg[0] + swsg[1];
        }
    }
}

// ---------------------------------------------------------------------------
// K2: 64 blocks: reduce 64 (min,max) pairs (redundant, cheap), bin 256 entro
//     elements each into shared histogram, flush to global. Last finished
//     block computes entropy + sigmoid mean + output, then recycles flags.
// ---------------------------------------------------------------------------
__global__ void __launch_bounds__(256) k_histout(float* __restrict__ out) {
    gds();   // wait for k_fused completion

    const int tid = threadIdx.x;

    __shared__ float smin[64], smax[64];
    __shared__ int hist[256];
    hist[tid] = 0;
    if (tid < 64) {
        smin[tid] = g_mm[tid * 2 + 0];
        smax[tid] = g_mm[tid * 2 + 1];
    }
    __syncthreads();
#pragma unroll
    for (int o = 32; o > 0; o >>= 1) {
        if (tid < o) {
            smin[tid] = fminf(smin[tid], smin[tid + o]);
            smax[tid] = fmaxf(smax[tid], smax[tid + o]);
        }
        __syncthreads();
    }
    const float emin = smin[0];
    const float denom = smax[0] - emin;

    float e = (g_entro[blockIdx.x * 256 + tid] - emin) / denom * 255.0f;
    int bin = (int)floorf(e * (256.0f / 255.0f));
    bin = min(max(bin, 0), 255);
    atomicAdd(&hist[bin], 1);
    __syncthreads();

    if (hist[tid] != 0) atomicAdd(&g_hist[tid], hist[tid]);
    __threadfence();

    __shared__ int islast;
    if (tid == 0) islast = (atomicAdd(&g_cnt, 1) == HIST_BLOCKS - 1) ? 1 : 0;
    __syncthreads();
    if (!islast) return;
    __threadfence();

    // recycle flags for the next graph replay (stream-ordered before it)
    if (tid < B_) { g_done[tid] = 0; g_cons[tid] = 0; }
    if (tid == 0) g_cnt = 0;

    // sigmoid-sum reduce (64 partials, deterministic tree)
    __shared__ double sd[64];
    if (tid < 64) sd[tid] = (double)g_ssum[tid];
    __syncthreads();
#pragma unroll
    for (int o = 32; o > 0; o >>= 1) {
        if (tid < o) sd[tid] += sd[tid + o];
        __syncthreads();
    }

    // entropy + nonzero count over global histogram
    __shared__ float ssum[256];
    __shared__ int   snz[256];
    int h = __ldcg(&g_hist[tid]);
    float hisv = (float)h * (1.0f / (float)HW_);
    ssum[tid] = hisv * (-logf(hisv + 1e-8f));
    snz[tid]  = (h != 0) ? 1 : 0;
    __syncthreads();
#pragma unroll
    for (int o = 128; o > 0; o >>= 1) {
        if (tid < o) {
            ssum[tid] += ssum[tid + o];
            snz[tid]  += snz[tid + o];
        }
        __syncthreads();
    }

    if (tid == 0) {
        float s = (float)(sd[0] / (double)((size_t)B_ * HW_));
        float entro_final = ssum[0] / (float)snz[0];
        out[0] = s + entro_final * 10.0f;
    }
}

// ---------------------------------------------------------------------------
static inline void launch_pdl(void* func, dim3 grid, dim3 block, void** args) {
    cudaLaunchConfig_t cfg = {};
    cfg.gridDim  = grid;
    cfg.blockDim = block;
    cfg.dynamicSmemBytes = 0;
    cfg.stream = 0;
    cudaLaunchAttribute attr[1];
    attr[0].id = cudaLaunchAttributeProgrammaticStreamSerialization;
    attr[0].val.programmaticStreamSerializationAllowed = 1;
    cfg.attrs = attr;
    cfg.numAttrs = 1;
    cudaLaunchKernelExC(&cfg, func, args);
}

extern "C" void kernel_launch(void* const* d_in, const int* in_sizes, int n_in,
                              void* d_out, int out_size) {
    const float* x = (const float*)d_in[0];
    float* out = (float*)d_out;

    k_fused<<<NCTA, 512>>>(x);
    {   // k_histout(out)
        void* args[] = { (void*)&out };
        launch_pdl((void*)k_histout, dim3(HIST_BLOCKS), dim3(256), args);
    }
}